// round 10
// baseline (speedup 1.0000x reference)
#include <cuda_runtime.h>
#include <cuda_bf16.h>
#include <cfloat>
#include <cstdint>

#define EPS_S   0.01f
#define INV_EPS 100.0f
#define LOG_MU  -6.93146200f   /* log(1/1024 + 1e-8) */
#define BN_EPS  1e-5f

typedef unsigned short ushort_t;

/* ---------------- scratch (device globals: no allocs allowed) -------------- */
__device__ float g_C[4 * 1024 * 1024];          /* cost matrix; later tblend NCHW */
__device__ float g_u[4096], g_v[4096];
__device__ float g_rnx[4096], g_rny[4096];
__device__ float g_t[4 * 1024 * 512];           /* t NHWC fp32 [pix][512] */
__device__ float g_a1[4 * 1024 * 256];
__device__ float g_a2[4 * 1024 * 256];
__device__ float g_alpha[4 * 1024 * 512];
__device__ float g_cm[2048], g_rs[2048];
__device__ float g_scale[512], g_shift[512];
__device__ float g_ps[256 * 256], g_pq[256 * 256];
__device__ unsigned g_cnt, g_gen;
/* bf16 split buffers */
__device__ ushort_t g_cTh[4 * 1024 * 512], g_cTl[4 * 1024 * 512];
__device__ ushort_t g_sTh[4 * 1024 * 512], g_sTl[4 * 1024 * 512];
__device__ ushort_t g_sfh[4 * 512 * 1024], g_sfl[4 * 512 * 1024];
__device__ ushort_t g_pih[4 * 1024 * 1024], g_pil[4 * 1024 * 1024];
__device__ ushort_t g_tth[4 * 1024 * 512], g_ttl[4 * 1024 * 512];
__device__ ushort_t g_b1h[4 * 1024 * 256], g_b1l[4 * 1024 * 256];
__device__ ushort_t g_b2h[4 * 1024 * 256], g_b2l[4 * 1024 * 256];
__device__ ushort_t g_w1h[9 * 256 * 1024], g_w1l[9 * 256 * 1024];
__device__ ushort_t g_w2h[9 * 256 * 256],  g_w2l[9 * 256 * 256];
__device__ ushort_t g_w3h[9 * 512 * 256],  g_w3l[9 * 512 * 256];

__device__ __forceinline__ uint32_t smem_u32(const void* p) {
    uint32_t a;
    asm("{ .reg .u64 t; cvta.to.shared.u64 t, %1; cvt.u32.u64 %0, t; }"
        : "=r"(a) : "l"(p));
    return a;
}
__device__ __forceinline__ void ldsm_x4(uint32_t& r0, uint32_t& r1,
                                        uint32_t& r2, uint32_t& r3, uint32_t a) {
    asm volatile("ldmatrix.sync.aligned.m8n8.x4.shared.b16 {%0,%1,%2,%3}, [%4];"
                 : "=r"(r0), "=r"(r1), "=r"(r2), "=r"(r3) : "r"(a));
}
__device__ __forceinline__ void mma_bf16(float& d0, float& d1, float& d2, float& d3,
                                         uint32_t a0, uint32_t a1, uint32_t a2, uint32_t a3,
                                         uint32_t b0, uint32_t b1) {
    asm volatile(
        "mma.sync.aligned.m16n8k16.row.col.f32.bf16.bf16.f32 "
        "{%0,%1,%2,%3}, {%4,%5,%6,%7}, {%8,%9}, {%0,%1,%2,%3};"
        : "+f"(d0), "+f"(d1), "+f"(d2), "+f"(d3)
        : "r"(a0), "r"(a1), "r"(a2), "r"(a3), "r"(b0), "r"(b1));
}
__device__ __forceinline__ void bsplit(float v, ushort_t& h, ushort_t& l) {
    __nv_bfloat16 hh = __float2bfloat16(v);
    float rem = v - __bfloat162float(hh);
    __nv_bfloat16 ll = __float2bfloat16(rem);
    h = __bfloat16_as_ushort(hh);
    l = __bfloat16_as_ushort(ll);
}
__device__ __forceinline__ float bf2f(ushort_t x) {
    return __bfloat162float(__ushort_as_bfloat16(x));
}
__device__ __forceinline__ float warpSum(float v) {
    #pragma unroll
    for (int o = 16; o; o >>= 1) v += __shfl_xor_sync(0xffffffffu, v, o);
    return v;
}

/* ============ HMMA bf16 split GEMM (verified core) ======================== */
template <int EPI>
__global__ __launch_bounds__(256) void hmma_gemm(
    const ushort_t* __restrict__ Ahi, const ushort_t* __restrict__ Alo,
    const ushort_t* __restrict__ Bhi, const ushort_t* __restrict__ Blo,
    int Mtot, int Ktot, int Nrows, int OS,
    const float* __restrict__ rnx, const float* __restrict__ rny,
    float* __restrict__ out, ushort_t* __restrict__ o2h, ushort_t* __restrict__ o2l) {
    __shared__ ushort_t sAh[128 * 40], sAl[128 * 40];
    __shared__ ushort_t sBh[64 * 40], sBl[64 * 40];
    int tid = threadIdx.x, wid = tid >> 5, lid = tid & 31;
    int b = blockIdx.z, m0 = blockIdx.x * 128, n0 = blockIdx.y * 64;
    int wm = wid & 3, wn = wid >> 2;
    size_t abase = (size_t)b * Mtot * Ktot;
    size_t bbase = (size_t)b * Nrows * Ktot;
    uint32_t uAh = smem_u32(sAh), uAl = smem_u32(sAl);
    uint32_t uBh = smem_u32(sBh), uBl = smem_u32(sBl);
    int arow = ((lid >> 3) & 1) * 8 + (lid & 7);
    int akof = (lid >> 4) * 8;
    int brow = (lid & 7) + ((lid >> 4) & 1) * 8;
    int bkof = ((lid >> 3) & 1) * 8;

    float d[2][4][4];
    #pragma unroll
    for (int i = 0; i < 2; i++)
        #pragma unroll
        for (int j = 0; j < 4; j++)
            #pragma unroll
            for (int q = 0; q < 4; q++) d[i][j][q] = 0.f;

    for (int k0 = 0; k0 < Ktot; k0 += 32) {
        #pragma unroll
        for (int l = 0; l < 2; l++) {
            int idx = tid + l * 256;
            int r = idx >> 2, seg = idx & 3;
            *(uint4*)(sAh + r * 40 + seg * 8) =
                *(const uint4*)(Ahi + abase + (size_t)(m0 + r) * Ktot + k0 + seg * 8);
            *(uint4*)(sAl + r * 40 + seg * 8) =
                *(const uint4*)(Alo + abase + (size_t)(m0 + r) * Ktot + k0 + seg * 8);
        }
        {
            int r = tid >> 2, seg = tid & 3;
            *(uint4*)(sBh + r * 40 + seg * 8) =
                *(const uint4*)(Bhi + bbase + (size_t)(n0 + r) * Ktot + k0 + seg * 8);
            *(uint4*)(sBl + r * 40 + seg * 8) =
                *(const uint4*)(Blo + bbase + (size_t)(n0 + r) * Ktot + k0 + seg * 8);
        }
        __syncthreads();
        #pragma unroll
        for (int ks = 0; ks < 2; ks++) {
            int kb = ks * 16;
            uint32_t ah[2][4], al[2][4];
            #pragma unroll
            for (int tm = 0; tm < 2; tm++) {
                uint32_t off = (uint32_t)((wm * 32 + tm * 16 + arow) * 80 + (kb + akof) * 2);
                ldsm_x4(ah[tm][0], ah[tm][1], ah[tm][2], ah[tm][3], uAh + off);
                ldsm_x4(al[tm][0], al[tm][1], al[tm][2], al[tm][3], uAl + off);
            }
            uint32_t bh[4][2], bl[4][2];
            #pragma unroll
            for (int p = 0; p < 2; p++) {
                uint32_t off = (uint32_t)((wn * 32 + p * 16 + brow) * 80 + (kb + bkof) * 2);
                ldsm_x4(bh[2 * p][0], bh[2 * p][1], bh[2 * p + 1][0], bh[2 * p + 1][1], uBh + off);
                ldsm_x4(bl[2 * p][0], bl[2 * p][1], bl[2 * p + 1][0], bl[2 * p + 1][1], uBl + off);
            }
            #pragma unroll
            for (int tm = 0; tm < 2; tm++)
                #pragma unroll
                for (int tn = 0; tn < 4; tn++) {
                    mma_bf16(d[tm][tn][0], d[tm][tn][1], d[tm][tn][2], d[tm][tn][3],
                             ah[tm][0], ah[tm][1], ah[tm][2], ah[tm][3], bh[tn][0], bh[tn][1]);
                    mma_bf16(d[tm][tn][0], d[tm][tn][1], d[tm][tn][2], d[tm][tn][3],
                             ah[tm][0], ah[tm][1], ah[tm][2], ah[tm][3], bl[tn][0], bl[tn][1]);
                    mma_bf16(d[tm][tn][0], d[tm][tn][1], d[tm][tn][2], d[tm][tn][3],
                             al[tm][0], al[tm][1], al[tm][2], al[tm][3], bh[tn][0], bh[tn][1]);
                }
        }
        __syncthreads();
    }
    int tq = lid >> 2, tr = lid & 3;
    #pragma unroll
    for (int tm = 0; tm < 2; tm++) {
        #pragma unroll
        for (int half = 0; half < 2; half++) {
            int r = m0 + wm * 32 + tm * 16 + tq + half * 8;
            #pragma unroll
            for (int tn = 0; tn < 4; tn++) {
                int col = n0 + wn * 32 + tn * 8 + 2 * tr;
                float v0 = d[tm][tn][2 * half], v1 = d[tm][tn][2 * half + 1];
                size_t oidx = ((size_t)b * Mtot + r) * OS + col;
                if (EPI == 1) {
                    float rx = rnx[(b << 10) + r];
                    float2 o;
                    o.x = 1.f - rx * rny[(b << 10) + col] * v0;
                    o.y = 1.f - rx * rny[(b << 10) + col + 1] * v1;
                    *(float2*)(out + oidx) = o;
                } else {
                    float2 o; o.x = v0; o.y = v1;
                    *(float2*)(out + oidx) = o;
                    ushort_t h0, l0, h1, l1;
                    bsplit(v0, h0, l0);
                    bsplit(v1, h1, l1);
                    *(uint32_t*)(o2h + oidx) = ((uint32_t)h1 << 16) | h0;
                    *(uint32_t*)(o2l + oidx) = ((uint32_t)l1 << 16) | l0;
                }
            }
        }
    }
}

/* ============ shifted-GEMM tensor conv (NHWC, split bf16) ================= */
__global__ __launch_bounds__(256) void conv_hmma(
    const ushort_t* __restrict__ Ah0, const ushort_t* __restrict__ Al0,
    const ushort_t* __restrict__ Ah1, const ushort_t* __restrict__ Al1,
    int csplit, int CI,
    const ushort_t* __restrict__ Wh, const ushort_t* __restrict__ Wl,
    int CO, const float* __restrict__ bias, int relu,
    float* __restrict__ out) {
    extern __shared__ unsigned char cs[];
    ushort_t* sIh = (ushort_t*)(cs);
    ushort_t* sIl = (ushort_t*)(cs + 16320);
    ushort_t* sBh = (ushort_t*)(cs + 32640);
    ushort_t* sBl = (ushort_t*)(cs + 48000);
    int tid = threadIdx.x, wid = tid >> 5, lid = tid & 31;
    int mt = blockIdx.x;
    int b = mt >> 3, r0 = (mt & 7) * 4;
    int n0 = blockIdx.y * 64;
    int wm = wid & 3, wn = wid >> 2;
    int arow = ((lid >> 3) & 1) * 8 + (lid & 7);
    int akof = (lid >> 4) * 8;
    int brow = (lid & 7) + ((lid >> 4) & 1) * 8;
    int bkof = ((lid >> 3) & 1) * 8;
    uint32_t uIh = smem_u32(sIh), uIl = smem_u32(sIl);
    uint32_t uBh = smem_u32(sBh), uBl = smem_u32(sBl);
    uint32_t aoff[2];
    #pragma unroll
    for (int tm = 0; tm < 2; tm++) {
        int p = wm * 32 + tm * 16 + arow;
        aoff[tm] = (uint32_t)(((p >> 5) * 34 + (p & 31)) * 80 + akof * 2);
    }
    uint32_t boff = (uint32_t)((wn * 32 + brow) * 80 + bkof * 2);

    float d[2][4][4];
    #pragma unroll
    for (int i = 0; i < 2; i++)
        #pragma unroll
        for (int j = 0; j < 4; j++)
            #pragma unroll
            for (int q = 0; q < 4; q++) d[i][j][q] = 0.f;

    for (int ch = 0; ch < CI; ch += 32) {
        const ushort_t* srcH;
        const ushort_t* srcL;
        int cw, coff;
        if (ch < csplit) { srcH = Ah0; srcL = Al0; cw = csplit; coff = ch; }
        else             { srcH = Ah1; srcL = Al1; cw = CI - csplit; coff = ch - csplit; }
        for (int idx = tid; idx < 816; idx += 256) {
            int sp = idx >> 2, seg = idx & 3;
            int srow = sp / 34, scol = sp - srow * 34;
            int gy = r0 - 1 + srow, gx = scol - 1;
            uint4 vh = make_uint4(0, 0, 0, 0), vl = make_uint4(0, 0, 0, 0);
            if ((unsigned)gy < 32u && (unsigned)gx < 32u) {
                size_t off = (size_t)(b * 1024 + (gy << 5) + gx) * cw + coff + seg * 8;
                vh = *(const uint4*)(srcH + off);
                vl = *(const uint4*)(srcL + off);
            }
            *(uint4*)(sIh + sp * 40 + seg * 8) = vh;
            *(uint4*)(sIl + sp * 40 + seg * 8) = vl;
        }
        #pragma unroll 1
        for (int ky = 0; ky < 3; ky++) {
            for (int idx = tid; idx < 768; idx += 256) {
                int kx = idx >> 8, rem = idx & 255, oc = rem >> 2, seg = rem & 3;
                size_t woff = ((size_t)((ky * 3 + kx) * CO + n0 + oc)) * CI + ch + seg * 8;
                *(uint4*)(sBh + (kx * 64 + oc) * 40 + seg * 8) = *(const uint4*)(Wh + woff);
                *(uint4*)(sBl + (kx * 64 + oc) * 40 + seg * 8) = *(const uint4*)(Wl + woff);
            }
            __syncthreads();
            #pragma unroll
            for (int kx = 0; kx < 3; kx++) {
                uint32_t shoff = (uint32_t)((ky * 34 + kx) * 80);
                #pragma unroll
                for (int ks = 0; ks < 2; ks++) {
                    uint32_t kso = (uint32_t)(ks * 32);
                    uint32_t ah[2][4], al[2][4];
                    #pragma unroll
                    for (int tm = 0; tm < 2; tm++) {
                        ldsm_x4(ah[tm][0], ah[tm][1], ah[tm][2], ah[tm][3],
                                uIh + aoff[tm] + shoff + kso);
                        ldsm_x4(al[tm][0], al[tm][1], al[tm][2], al[tm][3],
                                uIl + aoff[tm] + shoff + kso);
                    }
                    uint32_t bh[4][2], bl[4][2];
                    #pragma unroll
                    for (int p = 0; p < 2; p++) {
                        uint32_t off = boff + (uint32_t)(kx * 64 * 80 + p * 16 * 80) + kso;
                        ldsm_x4(bh[2 * p][0], bh[2 * p][1], bh[2 * p + 1][0], bh[2 * p + 1][1],
                                uBh + off);
                        ldsm_x4(bl[2 * p][0], bl[2 * p][1], bl[2 * p + 1][0], bl[2 * p + 1][1],
                                uBl + off);
                    }
                    #pragma unroll
                    for (int tm = 0; tm < 2; tm++)
                        #pragma unroll
                        for (int tn = 0; tn < 4; tn++) {
                            mma_bf16(d[tm][tn][0], d[tm][tn][1], d[tm][tn][2], d[tm][tn][3],
                                     ah[tm][0], ah[tm][1], ah[tm][2], ah[tm][3],
                                     bh[tn][0], bh[tn][1]);
                            mma_bf16(d[tm][tn][0], d[tm][tn][1], d[tm][tn][2], d[tm][tn][3],
                                     ah[tm][0], ah[tm][1], ah[tm][2], ah[tm][3],
                                     bl[tn][0], bl[tn][1]);
                            mma_bf16(d[tm][tn][0], d[tm][tn][1], d[tm][tn][2], d[tm][tn][3],
                                     al[tm][0], al[tm][1], al[tm][2], al[tm][3],
                                     bh[tn][0], bh[tn][1]);
                        }
                }
            }
            __syncthreads();
        }
    }
    int tq = lid >> 2, tr = lid & 3;
    #pragma unroll
    for (int tm = 0; tm < 2; tm++) {
        #pragma unroll
        for (int half = 0; half < 2; half++) {
            int pt = wm * 32 + tm * 16 + tq + half * 8;
            size_t prow = (size_t)(b * 1024 + r0 * 32 + pt) * CO;
            #pragma unroll
            for (int tn = 0; tn < 4; tn++) {
                int col = n0 + wn * 32 + tn * 8 + 2 * tr;
                float v0 = d[tm][tn][2 * half] + bias[col];
                float v1 = d[tm][tn][2 * half + 1] + bias[col + 1];
                if (relu) { v0 = fmaxf(v0, 0.f); v1 = fmaxf(v1, 0.f); }
                float2 o; o.x = v0; o.y = v1;
                *(float2*)(out + prow + col) = o;
            }
        }
    }
}
static const int CONV_SMEM = 63360;

/* ---------------- prep kernels ---------------- */
__global__ __launch_bounds__(256) void transpose_split(
    const float* __restrict__ x, ushort_t* __restrict__ oh, ushort_t* __restrict__ ol) {
    __shared__ float tb[32][33];
    int b = blockIdx.z;
    int i0 = blockIdx.x * 32, d0 = blockIdx.y * 32;
    int tx = threadIdx.x & 31, ty = threadIdx.x >> 5;
    const float* xb = x + (size_t)b * 512 * 1024;
    #pragma unroll
    for (int k = 0; k < 4; k++)
        tb[ty + k * 8][tx] = xb[(size_t)(d0 + ty + k * 8) * 1024 + i0 + tx];
    __syncthreads();
    #pragma unroll
    for (int k = 0; k < 4; k++) {
        int il = ty + k * 8;
        float v = tb[tx][il];
        ushort_t h, l;
        bsplit(v, h, l);
        size_t o = (size_t)b * 1024 * 512 + (size_t)(i0 + il) * 512 + d0 + tx;
        oh[o] = h; ol[o] = l;
    }
}

__global__ __launch_bounds__(256) void convert_split(
    const float* __restrict__ x, ushort_t* __restrict__ oh,
    ushort_t* __restrict__ ol, int npair) {
    int i = blockIdx.x * 256 + threadIdx.x;
    if (i >= npair) return;
    float2 v = ((const float2*)x)[i];
    ushort_t h0, l0, h1, l1;
    bsplit(v.x, h0, l0);
    bsplit(v.y, h1, l1);
    ((uint32_t*)oh)[i] = ((uint32_t)h1 << 16) | h0;
    ((uint32_t*)ol)[i] = ((uint32_t)l1 << 16) | l0;
}

__global__ __launch_bounds__(256) void rownorm_t(const ushort_t* __restrict__ xh,
                                                 const ushort_t* __restrict__ xl,
                                                 float* __restrict__ rn) {
    int row = blockIdx.x * 8 + (threadIdx.x >> 5);
    int lane = threadIdx.x & 31;
    const uint4* ph = (const uint4*)(xh + (size_t)row * 512);
    const uint4* pl = (const uint4*)(xl + (size_t)row * 512);
    float s = 0.f;
    #pragma unroll
    for (int k = 0; k < 2; k++) {
        uint4 h4 = ph[lane + k * 32], l4 = pl[lane + k * 32];
        const ushort_t* hh = (const ushort_t*)&h4;
        const ushort_t* ll = (const ushort_t*)&l4;
        #pragma unroll
        for (int j = 0; j < 8; j++) {
            float v = bf2f(hh[j]) + bf2f(ll[j]);
            s = fmaf(v, v, s);
        }
    }
    s = warpSum(s);
    if (lane == 0) rn[row] = rsqrtf(s);
}

__global__ __launch_bounds__(256) void wprep(const float* __restrict__ w,
                                             ushort_t* __restrict__ wh,
                                             ushort_t* __restrict__ wl,
                                             int CO, int CI) {
    int i = blockIdx.x * 256 + threadIdx.x;
    if (i >= CO * CI) return;
    int oc = i / CI, ci = i - oc * CI;
    #pragma unroll
    for (int k = 0; k < 9; k++) {
        float v = w[(size_t)i * 9 + k];
        ushort_t h, l;
        bsplit(v, h, l);
        size_t o = ((size_t)k * CO + oc) * CI + ci;
        wh[o] = h; wl[o] = l;
    }
}

/* ============ persistent Sinkhorn: init + 20 iters + pi, 1 launch ==========
   Grid MUST be <= 148 blocks (1 block/SM co-residency for the sw barrier).  */
__global__ __launch_bounds__(256) void sinkhorn_all(
    const float* __restrict__ C, float* __restrict__ u, float* __restrict__ v,
    ushort_t* __restrict__ ph, ushort_t* __restrict__ pl) {
    __shared__ float sm_[8][33], sq_[8][33];
    int tid = threadIdx.x, wid = tid >> 5, lane = tid & 31;
    int nb = gridDim.x, blk = blockIdx.x;
    __shared__ unsigned sgen;
    if (tid == 0) sgen = atomicAdd(&g_gen, 0u);
    __syncthreads();
    unsigned myg = sgen;

#define GRIDBAR() do {                                                         \
    __syncthreads();                                                           \
    if (tid == 0) {                                                            \
        __threadfence();                                                       \
        unsigned a = atomicAdd(&g_cnt, 1u);                                    \
        if (a == (unsigned)nb - 1u) {                                          \
            atomicExch(&g_cnt, 0u);                                            \
            __threadfence();                                                   \
            atomicExch(&g_gen, myg + 1u);                                      \
        } else {                                                               \
            while (atomicAdd(&g_gen, 0u) == myg) __nanosleep(100);             \
        }                                                                      \
        myg++;                                                                 \
        __threadfence();                                                       \
    }                                                                          \
    __syncthreads();                                                           \
} while (0)

    /* init: zero v */
    for (int z = blk * 256 + tid; z < 4096; z += nb * 256) v[z] = 0.f;
    GRIDBAR();

    for (int it = 0; it < 20; it++) {
        /* u phase: warp per row, online LSE over 1024 cols */
        for (int row = blk * 8 + wid; row < 4096; row += nb * 8) {
            const float4* Crow = (const float4*)(C + (size_t)row * 1024);
            const float4* vb = (const float4*)(v + ((row >> 10) << 10));
            float m = -FLT_MAX, s = 0.f;
            #pragma unroll 2
            for (int j4 = lane; j4 < 256; j4 += 32) {
                float4 c = Crow[j4], vv = vb[j4];
                float x0 = (vv.x - c.x) * INV_EPS;
                float x1 = (vv.y - c.y) * INV_EPS;
                float x2 = (vv.z - c.z) * INV_EPS;
                float x3 = (vv.w - c.w) * INV_EPS;
                float mx = fmaxf(fmaxf(x0, x1), fmaxf(x2, x3));
                float nm = fmaxf(m, mx);
                s = s * __expf(m - nm) + __expf(x0 - nm) + __expf(x1 - nm)
                    + __expf(x2 - nm) + __expf(x3 - nm);
                m = nm;
            }
            #pragma unroll
            for (int o = 16; o; o >>= 1) {
                float m2 = __shfl_xor_sync(0xffffffffu, m, o);
                float s2 = __shfl_xor_sync(0xffffffffu, s, o);
                float nm = fmaxf(m, m2);
                s = s * __expf(m - nm) + s2 * __expf(m2 - nm);
                m = nm;
            }
            if (lane == 0) u[row] = EPS_S * (LOG_MU - (m + __logf(s)));
        }
        GRIDBAR();
        /* v phase: 128 column-chunk blocks (32 j each) */
        if (blk < 128) {
            int b = blk >> 5, j = ((blk & 31) << 5) + (tid & 31);
            int ty = tid >> 5;
            const float* p = C + (size_t)b * 1048576 + j;
            const float* ub = u + (b << 10);
            float m0 = -FLT_MAX, s0 = 0.f, m1 = -FLT_MAX, s1 = 0.f;
            for (int i = ty; i < 1024; i += 16) {
                float xa = (ub[i] - p[(size_t)i << 10]) * INV_EPS;
                float xb = (ub[i + 8] - p[(size_t)(i + 8) << 10]) * INV_EPS;
                float n0 = fmaxf(m0, xa);
                s0 = s0 * __expf(m0 - n0) + __expf(xa - n0); m0 = n0;
                float n1 = fmaxf(m1, xb);
                s1 = s1 * __expf(m1 - n1) + __expf(xb - n1); m1 = n1;
            }
            float mm = fmaxf(m0, m1);
            float ss = s0 * __expf(m0 - mm) + s1 * __expf(m1 - mm);
            sm_[ty][tid & 31] = mm; sq_[ty][tid & 31] = ss;
            __syncthreads();
            if (ty == 0) {
                float M = mm, S = ss;
                #pragma unroll
                for (int q = 1; q < 8; q++) {
                    float m2 = sm_[q][tid & 31], s2 = sq_[q][tid & 31];
                    float nm = fmaxf(M, m2);
                    S = S * __expf(M - nm) + s2 * __expf(m2 - nm);
                    M = nm;
                }
                v[(b << 10) + j] = EPS_S * (LOG_MU - (M + __logf(S)));
            }
        }
        GRIDBAR();
    }
    /* pi phase: warp per row, split to bf16 hi/lo */
    for (int row = blk * 8 + wid; row < 4096; row += nb * 8) {
        float ui = u[row];
        const float4* Crow = (const float4*)(C + (size_t)row * 1024);
        const float4* vb = (const float4*)(v + ((row >> 10) << 10));
        uint2* phr = (uint2*)(ph + (size_t)row * 1024);
        uint2* plr = (uint2*)(pl + (size_t)row * 1024);
        for (int j4 = lane; j4 < 256; j4 += 32) {
            float4 c = Crow[j4], vv = vb[j4];
            float p0 = __expf((ui + vv.x - c.x) * INV_EPS) * 1024.f;
            float p1 = __expf((ui + vv.y - c.y) * INV_EPS) * 1024.f;
            float p2 = __expf((ui + vv.z - c.z) * INV_EPS) * 1024.f;
            float p3 = __expf((ui + vv.w - c.w) * INV_EPS) * 1024.f;
            ushort_t h0, l0, h1, l1, h2, l2, h3, l3;
            bsplit(p0, h0, l0); bsplit(p1, h1, l1);
            bsplit(p2, h2, l2); bsplit(p3, h3, l3);
            uint2 oh, ol;
            oh.x = ((uint32_t)h1 << 16) | h0; oh.y = ((uint32_t)h3 << 16) | h2;
            ol.x = ((uint32_t)l1 << 16) | l0; ol.y = ((uint32_t)l3 << 16) | l2;
            phr[j4] = oh; plr[j4] = ol;
        }
    }
#undef GRIDBAR
}

/* ---------------- per-(b,c) mean / 1/std of content (NCHW) ---------------- */
__global__ __launch_bounds__(128) void cmstd(const float* __restrict__ x,
                                             float* __restrict__ cm,
                                             float* __restrict__ rs) {
    int bc = blockIdx.x, t = threadIdx.x;
    const float* p = x + ((size_t)bc << 10);
    float s = 0.f, q = 0.f;
    #pragma unroll
    for (int l = 0; l < 8; l++) {
        float v = p[t + l * 128];
        s += v; q = fmaf(v, v, q);
    }
    s = warpSum(s); q = warpSum(q);
    __shared__ float rsm[4], rqm[4];
    if ((t & 31) == 0) { rsm[t >> 5] = s; rqm[t >> 5] = q; }
    __syncthreads();
    if (t == 0) {
        float S = rsm[0] + rsm[1] + rsm[2] + rsm[3];
        float Q = rqm[0] + rqm[1] + rqm[2] + rqm[3];
        float mean = S * (1.f / 1024.f);
        float var = Q * (1.f / 1024.f) - mean * mean;
        cm[bc] = mean;
        rs[bc] = rsqrtf(fmaxf(var, 0.f) + 1e-5f);
    }
}

/* ---------------- BatchNorm (NHWC, two-phase, deterministic) --------------- */
__global__ __launch_bounds__(256) void bnpart(const float* __restrict__ x,
                                              float* __restrict__ ps,
                                              float* __restrict__ pq) {
    int slab = blockIdx.x, t = threadIdx.x;
    float s = 0.f, q = 0.f;
    #pragma unroll
    for (int i = 0; i < 16; i++) {
        float v = x[(size_t)(slab * 16 + i) * 256 + t];
        s += v; q = fmaf(v, v, q);
    }
    ps[slab * 256 + t] = s;
    pq[slab * 256 + t] = q;
}
__global__ void bnfin(const float* __restrict__ ps, const float* __restrict__ pq,
                      const float* __restrict__ g, const float* __restrict__ be,
                      float* __restrict__ scale, float* __restrict__ shift) {
    int c = threadIdx.x;
    float s = 0.f, q = 0.f;
    for (int k = 0; k < 256; k++) { s += ps[k * 256 + c]; q += pq[k * 256 + c]; }
    float mean = s * (1.f / 4096.f);
    float var = q * (1.f / 4096.f) - mean * mean;
    float sc = g[c] * rsqrtf(fmaxf(var, 0.f) + BN_EPS);
    scale[c] = sc;
    shift[c] = be[c] - mean * sc;
}
__global__ __launch_bounds__(256) void bn_split(const float* __restrict__ x,
                                                const float* __restrict__ scale,
                                                const float* __restrict__ shift,
                                                ushort_t* __restrict__ oh,
                                                ushort_t* __restrict__ ol) {
    int i = blockIdx.x * 256 + threadIdx.x;
    int c = i & 255;
    float v = fmaf(x[i], scale[c], shift[c]);
    ushort_t h, l;
    bsplit(v, h, l);
    oh[i] = h; ol[i] = l;
}

/* -------- blend + transpose: tblend NCHW = t + alpha*(content-cm)*rs ------- */
__global__ __launch_bounds__(256) void blend_T(const float* __restrict__ tn,
                                               const float* __restrict__ an,
                                               const float* __restrict__ content,
                                               const float* __restrict__ cm,
                                               const float* __restrict__ rs,
                                               float* __restrict__ outc) {
    __shared__ float ts[32][33], as_[32][33];
    int pix0 = blockIdx.x * 32, ch0 = blockIdx.y * 32;
    int tx = threadIdx.x & 31, ty = threadIdx.x >> 5;
    #pragma unroll
    for (int k = 0; k < 4; k++) {
        int p = pix0 + ty + k * 8;
        ts[ty + k * 8][tx]  = tn[(size_t)p * 512 + ch0 + tx];
        as_[ty + k * 8][tx] = an[(size_t)p * 512 + ch0 + tx];
    }
    __syncthreads();
    int b = pix0 >> 10;
    int pl = pix0 & 1023;
    #pragma unroll
    for (int k = 0; k < 4; k++) {
        int cl = ty + k * 8;
        int gch = b * 512 + ch0 + cl;
        float m = cm[gch], r = rs[gch];
        float c = content[(size_t)gch * 1024 + pl + tx];
        float v = fmaf(as_[tx][cl], (c - m) * r, ts[tx][cl]);
        outc[(size_t)gch * 1024 + pl + tx] = v;
    }
}

/* ---------------- decoder: direct 3x3 conv NCHW ---------------- */
template <int OCT, int SROWS, int NT, int CIT>
__global__ __launch_bounds__(NT) void conv3x3(
    const float* __restrict__ src0, int CI, int CO,
    const float* __restrict__ W, const float* __restrict__ bias,
    float* __restrict__ out) {
    constexpr int NPIX = SROWS * 32;
    constexpr int PXT = NPIX / NT;
    __shared__ float s_in[CIT][SROWS + 2][34];
    __shared__ float s_w[CIT][9][OCT];
    int b = blockIdx.x, oc0 = blockIdx.y * OCT, r0 = blockIdx.z * SROWS;
    int tid = threadIdx.x;
    int rr[PXT], cc[PXT];
    #pragma unroll
    for (int p = 0; p < PXT; p++) {
        int px = tid + p * NT;
        rr[p] = px >> 5; cc[p] = px & 31;
    }
    float acc[OCT][PXT];
    #pragma unroll
    for (int o = 0; o < OCT; o++)
        #pragma unroll
        for (int p = 0; p < PXT; p++) acc[o][p] = 0.f;

    const int TOTIN = CIT * (SROWS + 2) * 34;
    const int TW = CIT * 9 * OCT;
    #pragma unroll 1
    for (int ci0 = 0; ci0 < CI; ci0 += CIT) {
        #pragma unroll 1
        for (int idx = tid; idx < TOTIN; idx += NT) {
            int ci = idx / ((SROWS + 2) * 34);
            int rem = idx - ci * ((SROWS + 2) * 34);
            int r = rem / 34, c = rem - r * 34;
            int gy = r0 + r - 1, gx = c - 1;
            float v = 0.f;
            if ((unsigned)gy < 32u && (unsigned)gx < 32u)
                v = src0[((size_t)(b * CI + ci0 + ci) << 10) + (gy << 5) + gx];
            (&s_in[0][0][0])[idx] = v;
        }
        #pragma unroll 1
        for (int idx = tid; idx < TW; idx += NT) {
            int ci = idx / (9 * OCT);
            int rem = idx - ci * (9 * OCT);
            int k = rem / OCT, oc = rem - k * OCT;
            float wv = 0.f;
            if (oc0 + oc < CO)
                wv = W[((size_t)(oc0 + oc) * CI + ci0 + ci) * 9 + k];
            (&s_w[0][0][0])[idx] = wv;
        }
        __syncthreads();
        #pragma unroll 1
        for (int ci = 0; ci < CIT; ci++) {
            #pragma unroll
            for (int ky = 0; ky < 3; ky++)
                #pragma unroll
                for (int kx = 0; kx < 3; kx++) {
                    float w[OCT];
                    #pragma unroll
                    for (int o4 = 0; o4 < OCT / 4; o4++)
                        *(float4*)&w[o4 * 4] = *(const float4*)&s_w[ci][ky * 3 + kx][o4 * 4];
                    #pragma unroll
                    for (int p = 0; p < PXT; p++) {
                        float v = s_in[ci][rr[p] + ky][cc[p] + kx];
                        #pragma unroll
                        for (int o = 0; o < OCT; o++)
                            acc[o][p] = fmaf(v, w[o], acc[o][p]);
                    }
                }
        }
        __syncthreads();
    }
    #pragma unroll
    for (int o = 0; o < OCT; o++) {
        if (oc0 + o >= CO) break;
        float bi = bias[oc0 + o];
        #pragma unroll
        for (int p = 0; p < PXT; p++)
            out[((size_t)(b * CO + oc0 + o) << 10) + r0 * 32 + tid + p * NT] = acc[o][p] + bi;
    }
}

/* ---------------- host orchestration ---------------- */
extern "C" void kernel_launch(void* const* d_in, const int* in_sizes, int n_in,
                              void* d_out, int out_size) {
    const float* content = (const float*)d_in[0];
    const float* style   = (const float*)d_in[1];
    const float* w1 = (const float*)d_in[2];  const float* b1 = (const float*)d_in[3];
    const float* g1 = (const float*)d_in[4];  const float* be1 = (const float*)d_in[5];
    const float* w2 = (const float*)d_in[6];  const float* b2 = (const float*)d_in[7];
    const float* g2 = (const float*)d_in[8];  const float* be2 = (const float*)d_in[9];
    const float* w3 = (const float*)d_in[10]; const float* b3 = (const float*)d_in[11];
    const float* dw = (const float*)d_in[12]; const float* db = (const float*)d_in[13];
    float* out = (float*)d_out;
    (void)in_sizes; (void)n_in; (void)out_size;

    float *pC, *pu, *pv, *prnx, *prny, *pt, *pa1, *pa2, *palpha, *pcm, *prs,
          *pscale, *pshift, *pps, *ppq;
    ushort_t *pcTh, *pcTl, *psTh, *psTl, *psfh, *psfl, *ppih, *ppil,
             *ptth, *pttl, *pb1h, *pb1l, *pb2h, *pb2l,
             *pw1h, *pw1l, *pw2h, *pw2l, *pw3h, *pw3l;
    cudaGetSymbolAddress((void**)&pC, g_C);
    cudaGetSymbolAddress((void**)&pu, g_u);
    cudaGetSymbolAddress((void**)&pv, g_v);
    cudaGetSymbolAddress((void**)&prnx, g_rnx);
    cudaGetSymbolAddress((void**)&prny, g_rny);
    cudaGetSymbolAddress((void**)&pt, g_t);
    cudaGetSymbolAddress((void**)&pa1, g_a1);
    cudaGetSymbolAddress((void**)&pa2, g_a2);
    cudaGetSymbolAddress((void**)&palpha, g_alpha);
    cudaGetSymbolAddress((void**)&pcm, g_cm);
    cudaGetSymbolAddress((void**)&prs, g_rs);
    cudaGetSymbolAddress((void**)&pscale, g_scale);
    cudaGetSymbolAddress((void**)&pshift, g_shift);
    cudaGetSymbolAddress((void**)&pps, g_ps);
    cudaGetSymbolAddress((void**)&ppq, g_pq);
    cudaGetSymbolAddress((void**)&pcTh, g_cTh);
    cudaGetSymbolAddress((void**)&pcTl, g_cTl);
    cudaGetSymbolAddress((void**)&psTh, g_sTh);
    cudaGetSymbolAddress((void**)&psTl, g_sTl);
    cudaGetSymbolAddress((void**)&psfh, g_sfh);
    cudaGetSymbolAddress((void**)&psfl, g_sfl);
    cudaGetSymbolAddress((void**)&ppih, g_pih);
    cudaGetSymbolAddress((void**)&ppil, g_pil);
    cudaGetSymbolAddress((void**)&ptth, g_tth);
    cudaGetSymbolAddress((void**)&pttl, g_ttl);
    cudaGetSymbolAddress((void**)&pb1h, g_b1h);
    cudaGetSymbolAddress((void**)&pb1l, g_b1l);
    cudaGetSymbolAddress((void**)&pb2h, g_b2h);
    cudaGetSymbolAddress((void**)&pb2l, g_b2l);
    cudaGetSymbolAddress((void**)&pw1h, g_w1h);
    cudaGetSymbolAddress((void**)&pw1l, g_w1l);
    cudaGetSymbolAddress((void**)&pw2h, g_w2h);
    cudaGetSymbolAddress((void**)&pw2l, g_w2l);
    cudaGetSymbolAddress((void**)&pw3h, g_w3h);
    cudaGetSymbolAddress((void**)&pw3l, g_w3l);

    cudaFuncSetAttribute(conv_hmma, cudaFuncAttributeMaxDynamicSharedMemorySize, CONV_SMEM);

    /* operand prep */
    transpose_split<<<dim3(32, 16, 4), 256>>>(content, pcTh, pcTl);
    transpose_split<<<dim3(32, 16, 4), 256>>>(style, psTh, psTl);
    convert_split<<<4096, 256>>>(style, psfh, psfl, 4 * 512 * 512);
    rownorm_t<<<512, 256>>>(pcTh, pcTl, prnx);
    rownorm_t<<<512, 256>>>(psTh, psTl, prny);
    wprep<<<1024, 256>>>(w1, pw1h, pw1l, 256, 1024);
    wprep<<<256, 256>>>(w2, pw2h, pw2l, 256, 256);
    wprep<<<512, 256>>>(w3, pw3h, pw3l, 512, 256);

    /* cosine-cost matrix */
    hmma_gemm<1><<<dim3(8, 16, 4), 256>>>(pcTh, pcTl, psTh, psTl,
        1024, 512, 1024, 1024, prnx, prny, pC, nullptr, nullptr);

    /* Sinkhorn (init + 20 iters + pi) in ONE persistent launch */
    sinkhorn_all<<<148, 256>>>(pC, pu, pv, ppih, ppil);

    /* t = pi @ style^T -> NHWC fp32 + bf16 split */
    hmma_gemm<2><<<dim3(8, 8, 4), 256>>>(ppih, ppil, psfh, psfl,
        1024, 1024, 512, 512, nullptr, nullptr, pt, ptth, pttl);

    cmstd<<<2048, 128>>>(content, pcm, prs);

    /* alpha predictor via tensor convs (NHWC) */
    conv_hmma<<<dim3(32, 4), 256, CONV_SMEM>>>(ptth, pttl, pcTh, pcTl, 512, 1024,
        pw1h, pw1l, 256, b1, 1, pa1);
    bnpart<<<256, 256>>>(pa1, pps, ppq);
    bnfin<<<1, 256>>>(pps, ppq, g1, be1, pscale, pshift);
    bn_split<<<4096, 256>>>(pa1, pscale, pshift, pb1h, pb1l);
    conv_hmma<<<dim3(32, 4), 256, CONV_SMEM>>>(pb1h, pb1l, pb1h, pb1l, 256, 256,
        pw2h, pw2l, 256, b2, 1, pa2);
    bnpart<<<256, 256>>>(pa2, pps, ppq);
    bnfin<<<1, 256>>>(pps, ppq, g2, be2, pscale, pshift);
    bn_split<<<4096, 256>>>(pa2, pscale, pshift, pb2h, pb2l);
    conv_hmma<<<dim3(32, 8), 256, CONV_SMEM>>>(pb2h, pb2l, pb2h, pb2l, 256, 256,
        pw3h, pw3l, 512, b3, 0, palpha);

    /* blend (transposed to NCHW), decoder conv */
    blend_T<<<dim3(128, 16), 256>>>(pt, palpha, content, pcm, prs, pC);
    conv3x3<4, 4, 128, 8><<<dim3(4, 1, 8), 128>>>(pC, 512, 3, dw, db, out);
}